// round 15
// baseline (speedup 1.0000x reference)
#include <cuda_runtime.h>
#include <cuda_fp16.h>
#include <cstdint>
#include <math.h>

#define LQ 8192
#define LK 8192
#define DIM 128
#define KCH 8
#define SCALE 0.08838834764831845f  // 1/sqrt(128)

#define STRQ 136  // fp16 elems per smem row, 128-wide tiles (272B, conflict-free)
#define STRP 72   // fp16 elems per smem row, 64-wide tiles (144B)

// ---------------- device scratch ----------------
__device__ __half g_qh[(size_t)LQ * DIM];
__device__ __half g_kh[(size_t)LK * DIM];
__device__ __half g_vth[(size_t)DIM * LK];          // V^T [d][k]
__device__ __half g_pf16[(size_t)LQ * LK];          // normalized P, fp16
__device__ float g_lpart[(size_t)LQ * 64];
__device__ float g_il[LQ];
__device__ float g_opart[(size_t)KCH * LQ * DIM];

// ---------------- helpers ----------------
__device__ __forceinline__ uint32_t smem_u32(const void* p) {
    uint32_t a;
    asm("{ .reg .u64 t; cvta.to.shared.u64 t, %1; cvt.u32.u64 %0, t; }" : "=r"(a) : "l"(p));
    return a;
}
__device__ __forceinline__ void ldsm4(uint32_t (&r)[4], uint32_t addr) {
    asm volatile("ldmatrix.sync.aligned.m8n8.x4.shared.b16 {%0,%1,%2,%3}, [%4];"
        : "=r"(r[0]), "=r"(r[1]), "=r"(r[2]), "=r"(r[3]) : "r"(addr));
}
__device__ __forceinline__ void mma16816(float (&c)[4], const uint32_t (&a)[4],
                                         uint32_t b0, uint32_t b1) {
    asm volatile("mma.sync.aligned.m16n8k16.row.col.f32.f16.f16.f32 "
        "{%0,%1,%2,%3}, {%4,%5,%6,%7}, {%8,%9}, {%0,%1,%2,%3};"
        : "+f"(c[0]), "+f"(c[1]), "+f"(c[2]), "+f"(c[3])
        : "r"(a[0]), "r"(a[1]), "r"(a[2]), "r"(a[3]), "r"(b0), "r"(b1));
}
__device__ __forceinline__ void cpasync16(uint32_t dst, const void* src) {
    asm volatile("cp.async.cg.shared.global [%0], [%1], 16;" :: "r"(dst), "l"(src));
}
#define CP_COMMIT() asm volatile("cp.async.commit_group;" ::: "memory")
#define CP_WAIT(N)  asm volatile("cp.async.wait_group %0;" :: "n"(N) : "memory")
__device__ __forceinline__ uint32_t h2u(__half2 h) { return *reinterpret_cast<uint32_t*>(&h); }

// ---------------------------------------------------------------------------
// prep: fp32 -> fp16 (Q prescaled, K, V transposed)
// ---------------------------------------------------------------------------
__global__ __launch_bounds__(256) void prep_kernel(const float* __restrict__ Q,
                                                   const float* __restrict__ K,
                                                   const float* __restrict__ V) {
    size_t i = (size_t)blockIdx.x * 256 + threadIdx.x;
    g_qh[i] = __float2half_rn(Q[i] * SCALE);
    g_kh[i] = __float2half_rn(K[i]);
    size_t kr = i >> 7, d = i & 127;
    g_vth[d * LK + kr] = __float2half_rn(V[i]);
}

// ---------------------------------------------------------------------------
// Kernel A1: row partial sums of e = exp(Qs @ K^T). 128m x 128n, NO store.
// MMA order identical to qk_store_kernel -> bit-identical e.
// ---------------------------------------------------------------------------
__global__ __launch_bounds__(256, 2) void qk_sums_kernel() {
    extern __shared__ __align__(16) char smem[];
    __half* Qh = (__half*)smem;            // [128][STRQ]
    __half* Kh = Qh + 128 * STRQ;          // [128][STRQ]

    const int tid = threadIdx.x, lane = tid & 31, wid = tid >> 5;
    const int m0 = blockIdx.y * 128, n0 = blockIdx.x * 128;

    const uint32_t qhb = smem_u32(Qh), khb = smem_u32(Kh);

#pragma unroll
    for (int i = 0; i < 8; i++) {
        int idx = i * 256 + tid;
        int row = idx >> 4, seg = idx & 15;
        cpasync16(qhb + row * 272 + seg * 16, g_qh + (size_t)(m0 + row) * DIM + seg * 8);
    }
#pragma unroll
    for (int i = 0; i < 8; i++) {
        int idx = i * 256 + tid;
        int row = idx >> 4, seg = idx & 15;
        cpasync16(khb + row * 272 + seg * 16, g_kh + (size_t)(n0 + row) * DIM + seg * 8);
    }
    CP_COMMIT();
    CP_WAIT(0);
    __syncthreads();

    const int wm = (wid >> 1) * 32, wn = (wid & 1) * 64;
    float c[2][8][4];
#pragma unroll
    for (int mi = 0; mi < 2; mi++)
#pragma unroll
        for (int nj = 0; nj < 8; nj++)
#pragma unroll
            for (int e = 0; e < 4; e++) c[mi][nj][e] = 0.f;

    const int arow = lane & 15;
    const int acol = (lane >> 4) * 8;

#pragma unroll
    for (int k16 = 0; k16 < 8; k16++) {
        const int kc = k16 * 16 + acol;
        uint32_t a[2][4], b[4][4];
#pragma unroll
        for (int mi = 0; mi < 2; mi++)
            ldsm4(a[mi], qhb + ((wm + mi * 16 + arow) * STRQ + kc) * 2);
#pragma unroll
        for (int nj = 0; nj < 4; nj++)
            ldsm4(b[nj], khb + ((wn + nj * 16 + arow) * STRQ + kc) * 2);
#pragma unroll
        for (int mi = 0; mi < 2; mi++)
#pragma unroll
            for (int nj = 0; nj < 4; nj++) {
                mma16816(c[mi][2 * nj], a[mi], b[nj][0], b[nj][2]);
                mma16816(c[mi][2 * nj + 1], a[mi], b[nj][1], b[nj][3]);
            }
    }

#pragma unroll
    for (int mi = 0; mi < 2; mi++)
#pragma unroll
        for (int nj = 0; nj < 8; nj++)
#pragma unroll
            for (int e = 0; e < 4; e++) c[mi][nj][e] = __expf(c[mi][nj][e]);

    __syncthreads();
    float* rs = (float*)smem;  // [128][2]
#pragma unroll
    for (int mi = 0; mi < 2; mi++) {
        float v0 = 0.f, v1 = 0.f;
#pragma unroll
        for (int nj = 0; nj < 8; nj++) {
            v0 += c[mi][nj][0] + c[mi][nj][1];
            v1 += c[mi][nj][2] + c[mi][nj][3];
        }
        v0 += __shfl_xor_sync(0xffffffffu, v0, 1);
        v0 += __shfl_xor_sync(0xffffffffu, v0, 2);
        v1 += __shfl_xor_sync(0xffffffffu, v1, 1);
        v1 += __shfl_xor_sync(0xffffffffu, v1, 2);
        if ((lane & 3) == 0) {
            int r = wm + mi * 16 + (lane >> 2);
            rs[r * 2 + (wid & 1)] = v0;
            rs[(r + 8) * 2 + (wid & 1)] = v1;
        }
    }
    __syncthreads();
    if (tid < 128) {
        g_lpart[(size_t)(m0 + tid) * 64 + blockIdx.x] = rs[tid * 2] + rs[tid * 2 + 1];
    }
}

// ---------------------------------------------------------------------------
// Kernel B: l = sum of partials (fixed order), store 1/l.
// ---------------------------------------------------------------------------
__global__ __launch_bounds__(256) void lred_kernel() {
    const int row = blockIdx.x * 256 + threadIdx.x;
    const float4* p = (const float4*)(g_lpart + (size_t)row * 64);
    float s = 0.f;
#pragma unroll
    for (int i = 0; i < 16; i++) {
        float4 v = p[i];
        s += v.x + v.y + v.z + v.w;
    }
    g_il[row] = 1.0f / s;
}

// ---------------------------------------------------------------------------
// Kernel A2: recompute QK (identical order), p = exp(s)*il, write att fp32
// (final, normalized) AND P fp16 copy for the PV pass.
// ---------------------------------------------------------------------------
__global__ __launch_bounds__(256, 2) void qk_store_kernel(float* __restrict__ att) {
    extern __shared__ __align__(16) char smem[];
    __half* Qh = (__half*)smem;            // [128][STRQ]
    __half* Kh = Qh + 128 * STRQ;          // [128][STRQ]

    const int tid = threadIdx.x, lane = tid & 31, wid = tid >> 5;
    const int m0 = blockIdx.y * 128, n0 = blockIdx.x * 128;

    const uint32_t qhb = smem_u32(Qh), khb = smem_u32(Kh);

#pragma unroll
    for (int i = 0; i < 8; i++) {
        int idx = i * 256 + tid;
        int row = idx >> 4, seg = idx & 15;
        cpasync16(qhb + row * 272 + seg * 16, g_qh + (size_t)(m0 + row) * DIM + seg * 8);
    }
#pragma unroll
    for (int i = 0; i < 8; i++) {
        int idx = i * 256 + tid;
        int row = idx >> 4, seg = idx & 15;
        cpasync16(khb + row * 272 + seg * 16, g_kh + (size_t)(n0 + row) * DIM + seg * 8);
    }
    CP_COMMIT();
    CP_WAIT(0);
    __syncthreads();

    const int wm = (wid >> 1) * 32, wn = (wid & 1) * 64;
    float c[2][8][4];
#pragma unroll
    for (int mi = 0; mi < 2; mi++)
#pragma unroll
        for (int nj = 0; nj < 8; nj++)
#pragma unroll
            for (int e = 0; e < 4; e++) c[mi][nj][e] = 0.f;

    const int arow = lane & 15;
    const int acol = (lane >> 4) * 8;

#pragma unroll
    for (int k16 = 0; k16 < 8; k16++) {
        const int kc = k16 * 16 + acol;
        uint32_t a[2][4], b[4][4];
#pragma unroll
        for (int mi = 0; mi < 2; mi++)
            ldsm4(a[mi], qhb + ((wm + mi * 16 + arow) * STRQ + kc) * 2);
#pragma unroll
        for (int nj = 0; nj < 4; nj++)
            ldsm4(b[nj], khb + ((wn + nj * 16 + arow) * STRQ + kc) * 2);
#pragma unroll
        for (int mi = 0; mi < 2; mi++)
#pragma unroll
            for (int nj = 0; nj < 4; nj++) {
                mma16816(c[mi][2 * nj], a[mi], b[nj][0], b[nj][2]);
                mma16816(c[mi][2 * nj + 1], a[mi], b[nj][1], b[nj][3]);
            }
    }

    const int r0 = lane >> 2, c0 = (lane & 3) * 2;
    const float il00 = g_il[m0 + wm + r0];
    const float il01 = g_il[m0 + wm + r0 + 8];
    const float il10 = g_il[m0 + wm + 16 + r0];
    const float il11 = g_il[m0 + wm + 16 + r0 + 8];

    // p = exp(s)*il; write att fp32 + P fp16
#pragma unroll
    for (int mi = 0; mi < 2; mi++) {
        const float ia = (mi == 0) ? il00 : il10;
        const float ib = (mi == 0) ? il01 : il11;
#pragma unroll
        for (int nj = 0; nj < 8; nj++) {
            float p0 = __expf(c[mi][nj][0]) * ia;
            float p1 = __expf(c[mi][nj][1]) * ia;
            float p2 = __expf(c[mi][nj][2]) * ib;
            float p3 = __expf(c[mi][nj][3]) * ib;
            size_t row = (size_t)(m0 + wm + mi * 16 + r0);
            size_t col = (size_t)(n0 + wn + nj * 8 + c0);
            *(float2*)(att + row * LK + col) = make_float2(p0, p1);
            *(float2*)(att + (row + 8) * LK + col) = make_float2(p2, p3);
            *(uint32_t*)(g_pf16 + row * LK + col) = h2u(__floats2half2_rn(p0, p1));
            *(uint32_t*)(g_pf16 + (row + 8) * LK + col) = h2u(__floats2half2_rn(p2, p3));
        }
    }
}

// ---------------------------------------------------------------------------
// Kernel C: O = P @ V, pure fp16 GEMM. P/V stream through 3-deep cp.async
// rings. CTA 512 threads, 128q x 128d; 16 warps in 8q x 2d grid.
// ---------------------------------------------------------------------------
__global__ __launch_bounds__(512, 1) void pv_hmma_kernel() {
    extern __shared__ __align__(16) char smem[];
    const uint32_t pb = smem_u32(smem);                // P: 3 x [128][STRP] fp16
    const uint32_t vbb = pb + 3 * 128 * STRP * 2;      // V: 3 x [128][STRP] fp16
    const int BUF = 128 * STRP * 2;

    const int tid = threadIdx.x, lane = tid & 31, wid = tid >> 5;
    const int q0 = blockIdx.y * 128;
    const int kcnk = blockIdx.x;
    const int kbase = kcnk * (LK / KCH);

    const int qg = (wid & 7) * 16;
    const int dh = (wid >> 3) * 64;
    const int r0 = lane >> 2, c0 = (lane & 3) * 2;
    const int arow = lane & 15, acol = (lane >> 4) * 8;

    // prologue: stages 0,1
#pragma unroll
    for (int st = 0; st < 2; st++) {
        const int kb = kbase + st * 64;
#pragma unroll
        for (int i = 0; i < 2; i++) {
            int idx = i * 512 + tid;
            int row = idx >> 3, seg = idx & 7;
            cpasync16(pb + st * BUF + row * (STRP * 2) + seg * 16,
                      g_pf16 + (size_t)(q0 + row) * LK + kb + seg * 8);
        }
#pragma unroll
        for (int i = 0; i < 2; i++) {
            int idx = i * 512 + tid;
            int row = idx >> 3, seg = idx & 7;
            cpasync16(vbb + st * BUF + row * (STRP * 2) + seg * 16,
                      g_vth + (size_t)row * LK + kb + seg * 8);
        }
        CP_COMMIT();
    }

    float o[8][4];
#pragma unroll
    for (int nj = 0; nj < 8; nj++)
#pragma unroll
        for (int e = 0; e < 4; e++) o[nj][e] = 0.f;

    for (int t = 0; t < 16; t++) {
        CP_WAIT(1);
        __syncthreads();

        if (t < 14) {
            const int slot = (t + 2) % 3;
            const int kbn = kbase + (t + 2) * 64;
#pragma unroll
            for (int i = 0; i < 2; i++) {
                int idx = i * 512 + tid;
                int row = idx >> 3, seg = idx & 7;
                cpasync16(pb + slot * BUF + row * (STRP * 2) + seg * 16,
                          g_pf16 + (size_t)(q0 + row) * LK + kbn + seg * 8);
            }
#pragma unroll
            for (int i = 0; i < 2; i++) {
                int idx = i * 512 + tid;
                int row = idx >> 3, seg = idx & 7;
                cpasync16(vbb + slot * BUF + row * (STRP * 2) + seg * 16,
                          g_vth + (size_t)row * LK + kbn + seg * 8);
            }
        }
        CP_COMMIT();

        const uint32_t pcur = pb + (t % 3) * BUF;
        const uint32_t vcur = vbb + (t % 3) * BUF;

#pragma unroll
        for (int k16 = 0; k16 < 4; k16++) {
            const int kc = k16 * 16 + acol;
            uint32_t ah[4];
            ldsm4(ah, pcur + ((qg + arow) * STRP + kc) * 2);
#pragma unroll
            for (int nj = 0; nj < 4; nj++) {
                uint32_t bv[4];
                ldsm4(bv, vcur + ((dh + nj * 16 + arow) * STRP + kc) * 2);
                mma16816(o[2 * nj], ah, bv[0], bv[2]);
                mma16816(o[2 * nj + 1], ah, bv[1], bv[3]);
            }
        }
    }

    float* op = g_opart + (size_t)kcnk * ((size_t)LQ * DIM);
#pragma unroll
    for (int n8 = 0; n8 < 8; n8++) {
        size_t row = (size_t)(q0 + qg + r0);
        size_t col = (size_t)(dh + n8 * 8 + c0);
        *(float2*)(op + row * DIM + col) = make_float2(o[n8][0], o[n8][1]);
        *(float2*)(op + (row + 8) * DIM + col) = make_float2(o[n8][2], o[n8][3]);
    }
}

// ---------------------------------------------------------------------------
// Kernel D: reduce KCH partials into out (P pre-normalized -> plain sum).
// ---------------------------------------------------------------------------
__global__ __launch_bounds__(256) void reduce_kernel(float* __restrict__ out) {
    const size_t i = (size_t)blockIdx.x * 256 + threadIdx.x;
    float s = 0.f;
#pragma unroll
    for (int c = 0; c < KCH; c++) s += g_opart[(size_t)c * LQ * DIM + i];
    out[i] = s;
}

// ---------------------------------------------------------------------------
extern "C" void kernel_launch(void* const* d_in, const int* in_sizes, int n_in,
                              void* d_out, int out_size) {
    const float* Q = (const float*)d_in[0];
    const float* K = (const float*)d_in[1];
    const float* V = (const float*)d_in[2];
    float* out = (float*)d_out;             // [LQ, DIM]
    float* att = out + (size_t)LQ * DIM;    // [LQ, LK]

    const int smemA = 2 * 128 * STRQ * 2;       // 69632
    const int smemC = 6 * 128 * STRP * 2;       // 110592
    cudaFuncSetAttribute(qk_sums_kernel, cudaFuncAttributeMaxDynamicSharedMemorySize, smemA);
    cudaFuncSetAttribute(qk_store_kernel, cudaFuncAttributeMaxDynamicSharedMemorySize, smemA);
    cudaFuncSetAttribute(pv_hmma_kernel, cudaFuncAttributeMaxDynamicSharedMemorySize, smemC);

    prep_kernel<<<(LQ * DIM) / 256, 256>>>(Q, K, V);
    qk_sums_kernel<<<dim3(LK / 128, LQ / 128), 256, smemA>>>();
    lred_kernel<<<LQ / 256, 256>>>();
    qk_store_kernel<<<dim3(LK / 128, LQ / 128), 256, smemA>>>(att);
    pv_hmma_kernel<<<dim3(KCH, LQ / 128), 512, smemC>>>();
    reduce_kernel<<<(LQ * DIM) / 256, 256>>>(out);
}

// round 16
// speedup vs baseline: 1.2453x; 1.2453x over previous
#include <cuda_runtime.h>
#include <cuda_fp16.h>
#include <cstdint>
#include <math.h>

#define LQ 8192
#define LK 8192
#define DIM 128
#define KCH 8
#define SCALE 0.08838834764831845f  // 1/sqrt(128)

#define STRQ 136  // fp16 elems per smem row, 128-wide tiles (272B, conflict-free)
#define STRP 72   // fp16 elems per smem row, 64-wide tiles (144B)

// ---------------- device scratch ----------------
__device__ __half g_qh[(size_t)LQ * DIM];
__device__ __half g_kh[(size_t)LK * DIM];
__device__ __half g_vth[(size_t)DIM * LK];          // V^T [d][k]
__device__ __half g_ef16[(size_t)LQ * LK];          // unnormalized e, fp16
__device__ float g_lpart[(size_t)LQ * 64];
__device__ float g_il[LQ];
__device__ float g_opart[(size_t)KCH * LQ * DIM];

// ---------------- helpers ----------------
__device__ __forceinline__ uint32_t smem_u32(const void* p) {
    uint32_t a;
    asm("{ .reg .u64 t; cvta.to.shared.u64 t, %1; cvt.u32.u64 %0, t; }" : "=r"(a) : "l"(p));
    return a;
}
__device__ __forceinline__ void ldsm4(uint32_t (&r)[4], uint32_t addr) {
    asm volatile("ldmatrix.sync.aligned.m8n8.x4.shared.b16 {%0,%1,%2,%3}, [%4];"
        : "=r"(r[0]), "=r"(r[1]), "=r"(r[2]), "=r"(r[3]) : "r"(addr));
}
__device__ __forceinline__ void mma16816(float (&c)[4], const uint32_t (&a)[4],
                                         uint32_t b0, uint32_t b1) {
    asm volatile("mma.sync.aligned.m16n8k16.row.col.f32.f16.f16.f32 "
        "{%0,%1,%2,%3}, {%4,%5,%6,%7}, {%8,%9}, {%0,%1,%2,%3};"
        : "+f"(c[0]), "+f"(c[1]), "+f"(c[2]), "+f"(c[3])
        : "r"(a[0]), "r"(a[1]), "r"(a[2]), "r"(a[3]), "r"(b0), "r"(b1));
}
__device__ __forceinline__ void cpasync16(uint32_t dst, const void* src) {
    asm volatile("cp.async.cg.shared.global [%0], [%1], 16;" :: "r"(dst), "l"(src));
}
#define CP_COMMIT() asm volatile("cp.async.commit_group;" ::: "memory")
#define CP_WAIT(N)  asm volatile("cp.async.wait_group %0;" :: "n"(N) : "memory")
__device__ __forceinline__ uint32_t h2u(__half2 h) { return *reinterpret_cast<uint32_t*>(&h); }

// ---------------------------------------------------------------------------
// prep: fp32 -> fp16 (Q prescaled, K, V transposed)
// ---------------------------------------------------------------------------
__global__ __launch_bounds__(256) void prep_kernel(const float* __restrict__ Q,
                                                   const float* __restrict__ K,
                                                   const float* __restrict__ V) {
    size_t i = (size_t)blockIdx.x * 256 + threadIdx.x;
    g_qh[i] = __float2half_rn(Q[i] * SCALE);
    g_kh[i] = __float2half_rn(K[i]);
    size_t kr = i >> 7, d = i & 127;
    g_vth[d * LK + kr] = __float2half_rn(V[i]);
}

// ---------------------------------------------------------------------------
// Kernel A: e = exp(Qs @ K^T) -> g_ef16 (fp16) + fp32 per-row partial sums.
// 128m x 128n per CTA, warp tile 32m x 64n.
// ---------------------------------------------------------------------------
__global__ __launch_bounds__(256, 2) void qk_hmma_kernel() {
    extern __shared__ __align__(16) char smem[];
    __half* Qh = (__half*)smem;            // [128][STRQ]
    __half* Kh = Qh + 128 * STRQ;          // [128][STRQ]

    const int tid = threadIdx.x, lane = tid & 31, wid = tid >> 5;
    const int m0 = blockIdx.y * 128, n0 = blockIdx.x * 128;

    const uint32_t qhb = smem_u32(Qh), khb = smem_u32(Kh);

#pragma unroll
    for (int i = 0; i < 8; i++) {
        int idx = i * 256 + tid;
        int row = idx >> 4, seg = idx & 15;
        cpasync16(qhb + row * 272 + seg * 16, g_qh + (size_t)(m0 + row) * DIM + seg * 8);
    }
#pragma unroll
    for (int i = 0; i < 8; i++) {
        int idx = i * 256 + tid;
        int row = idx >> 4, seg = idx & 15;
        cpasync16(khb + row * 272 + seg * 16, g_kh + (size_t)(n0 + row) * DIM + seg * 8);
    }
    CP_COMMIT();
    CP_WAIT(0);
    __syncthreads();

    const int wm = (wid >> 1) * 32, wn = (wid & 1) * 64;
    float c[2][8][4];
#pragma unroll
    for (int mi = 0; mi < 2; mi++)
#pragma unroll
        for (int nj = 0; nj < 8; nj++)
#pragma unroll
            for (int e = 0; e < 4; e++) c[mi][nj][e] = 0.f;

    const int arow = lane & 15;
    const int acol = (lane >> 4) * 8;

#pragma unroll
    for (int k16 = 0; k16 < 8; k16++) {
        const int kc = k16 * 16 + acol;
        uint32_t a[2][4], b[4][4];
#pragma unroll
        for (int mi = 0; mi < 2; mi++)
            ldsm4(a[mi], qhb + ((wm + mi * 16 + arow) * STRQ + kc) * 2);
#pragma unroll
        for (int nj = 0; nj < 4; nj++)
            ldsm4(b[nj], khb + ((wn + nj * 16 + arow) * STRQ + kc) * 2);
#pragma unroll
        for (int mi = 0; mi < 2; mi++)
#pragma unroll
            for (int nj = 0; nj < 4; nj++) {
                mma16816(c[mi][2 * nj], a[mi], b[nj][0], b[nj][2]);
                mma16816(c[mi][2 * nj + 1], a[mi], b[nj][1], b[nj][3]);
            }
    }

    // exp in place
#pragma unroll
    for (int mi = 0; mi < 2; mi++)
#pragma unroll
        for (int nj = 0; nj < 8; nj++)
#pragma unroll
            for (int e = 0; e < 4; e++) c[mi][nj][e] = __expf(c[mi][nj][e]);

    // store e as fp16
    const int r0 = lane >> 2, c0 = (lane & 3) * 2;
#pragma unroll
    for (int mi = 0; mi < 2; mi++) {
#pragma unroll
        for (int nj = 0; nj < 8; nj++) {
            size_t row = (size_t)(m0 + wm + mi * 16 + r0);
            size_t col = (size_t)(n0 + wn + nj * 8 + c0);
            *(uint32_t*)(g_ef16 + row * LK + col) = h2u(__floats2half2_rn(c[mi][nj][0], c[mi][nj][1]));
            *(uint32_t*)(g_ef16 + (row + 8) * LK + col) = h2u(__floats2half2_rn(c[mi][nj][2], c[mi][nj][3]));
        }
    }

    // deterministic per-row partial sums (fp32 e, same as before)
    __syncthreads();
    float* rs = (float*)smem;  // [128][2]
#pragma unroll
    for (int mi = 0; mi < 2; mi++) {
        float v0 = 0.f, v1 = 0.f;
#pragma unroll
        for (int nj = 0; nj < 8; nj++) {
            v0 += c[mi][nj][0] + c[mi][nj][1];
            v1 += c[mi][nj][2] + c[mi][nj][3];
        }
        v0 += __shfl_xor_sync(0xffffffffu, v0, 1);
        v0 += __shfl_xor_sync(0xffffffffu, v0, 2);
        v1 += __shfl_xor_sync(0xffffffffu, v1, 1);
        v1 += __shfl_xor_sync(0xffffffffu, v1, 2);
        if ((lane & 3) == 0) {
            int r = wm + mi * 16 + (lane >> 2);
            rs[r * 2 + (wid & 1)] = v0;
            rs[(r + 8) * 2 + (wid & 1)] = v1;
        }
    }
    __syncthreads();
    if (tid < 128) {
        g_lpart[(size_t)(m0 + tid) * 64 + blockIdx.x] = rs[tid * 2] + rs[tid * 2 + 1];
    }
}

// ---------------------------------------------------------------------------
// Kernel B: l = sum of partials (fixed order), store 1/l.
// ---------------------------------------------------------------------------
__global__ __launch_bounds__(256) void lred_kernel() {
    const int row = blockIdx.x * 256 + threadIdx.x;
    const float4* p = (const float4*)(g_lpart + (size_t)row * 64);
    float s = 0.f;
#pragma unroll
    for (int i = 0; i < 16; i++) {
        float4 v = p[i];
        s += v.x + v.y + v.z + v.w;
    }
    g_il[row] = 1.0f / s;
}

// ---------------------------------------------------------------------------
// Kernel C: streams fp16 e + V through 3-deep cp.async rings.
//   a) att = fp16(e) * il written as fp32 (disjoint tid-partition, float4)
//   b) O_unnorm += e @ V via direct ldsm of the fp16 e tiles (no cvt)
// CTA 512 threads, 128q x 128d; 16 warps in 8q x 2d grid.
// ---------------------------------------------------------------------------
__global__ __launch_bounds__(512, 1) void pv_hmma_kernel(float* __restrict__ att) {
    extern __shared__ __align__(16) char smem[];
    const uint32_t pb = smem_u32(smem);                 // e: 3 x [128][STRP] fp16
    __half* Ps = (__half*)smem;
    const uint32_t vbb = pb + 3 * 128 * STRP * 2;       // V: 3 x [128][STRP] fp16
    float* ilrow = (float*)(smem + 6 * 128 * STRP * 2); // [128]
    const int BUF = 128 * STRP * 2;

    const int tid = threadIdx.x, lane = tid & 31, wid = tid >> 5;
    const int q0 = blockIdx.y * 128;
    const int kcnk = blockIdx.x;
    const int kbase = kcnk * (LK / KCH);

    const int qg = (wid & 7) * 16;
    const int dh = (wid >> 3) * 64;
    const int r0 = lane >> 2, c0 = (lane & 3) * 2;
    const int arow = lane & 15, acol = (lane >> 4) * 8;

    if (tid < 128) ilrow[tid] = g_il[q0 + tid];

    // prologue: stages 0,1
#pragma unroll
    for (int st = 0; st < 2; st++) {
        const int kb = kbase + st * 64;
#pragma unroll
        for (int i = 0; i < 2; i++) {
            int idx = i * 512 + tid;
            int row = idx >> 3, seg = idx & 7;
            cpasync16(pb + st * BUF + row * (STRP * 2) + seg * 16,
                      g_ef16 + (size_t)(q0 + row) * LK + kb + seg * 8);
        }
#pragma unroll
        for (int i = 0; i < 2; i++) {
            int idx = i * 512 + tid;
            int row = idx >> 3, seg = idx & 7;
            cpasync16(vbb + st * BUF + row * (STRP * 2) + seg * 16,
                      g_vth + (size_t)row * LK + kb + seg * 8);
        }
        CP_COMMIT();
    }

    float o[8][4];
#pragma unroll
    for (int nj = 0; nj < 8; nj++)
#pragma unroll
        for (int e = 0; e < 4; e++) o[nj][e] = 0.f;

    for (int t = 0; t < 16; t++) {
        CP_WAIT(1);
        __syncthreads();

        if (t < 14) {
            const int slot = (t + 2) % 3;
            const int kbn = kbase + (t + 2) * 64;
#pragma unroll
            for (int i = 0; i < 2; i++) {
                int idx = i * 512 + tid;
                int row = idx >> 3, seg = idx & 7;
                cpasync16(pb + slot * BUF + row * (STRP * 2) + seg * 16,
                          g_ef16 + (size_t)(q0 + row) * LK + kbn + seg * 8);
            }
#pragma unroll
            for (int i = 0; i < 2; i++) {
                int idx = i * 512 + tid;
                int row = idx >> 3, seg = idx & 7;
                cpasync16(vbb + slot * BUF + row * (STRP * 2) + seg * 16,
                          g_vth + (size_t)row * LK + kbn + seg * 8);
            }
        }
        CP_COMMIT();

        const int kb = kbase + t * 64;
        const __half* Pc = Ps + (t % 3) * 128 * STRP;
        const uint32_t pcur = pb + (t % 3) * BUF;
        const uint32_t vcur = vbb + (t % 3) * BUF;

        // a) att write-back: fp16 e -> fp32 normalized, float4 stores
#pragma unroll
        for (int i = 0; i < 4; i++) {
            int idx = i * 512 + tid;
            int row = idx >> 4, col4 = (idx & 15) * 4;
            const __half2* hp = (const __half2*)(Pc + row * STRP + col4);
            __half2 e01 = hp[0], e23 = hp[1];
            const float il = ilrow[row];
            float4 s;
            s.x = __low2float(e01) * il;
            s.y = __high2float(e01) * il;
            s.z = __low2float(e23) * il;
            s.w = __high2float(e23) * il;
            *(float4*)(att + (size_t)(q0 + row) * LK + kb + col4) = s;
        }

        // b) MMA: A-frags via ldsm straight from fp16 e smem
#pragma unroll
        for (int k16 = 0; k16 < 4; k16++) {
            const int kc = k16 * 16 + acol;
            uint32_t ah[4];
            ldsm4(ah, pcur + ((qg + arow) * STRP + kc) * 2);
#pragma unroll
            for (int nj = 0; nj < 4; nj++) {
                uint32_t bv[4];
                ldsm4(bv, vcur + ((dh + nj * 16 + arow) * STRP + kc) * 2);
                mma16816(o[2 * nj], ah, bv[0], bv[2]);
                mma16816(o[2 * nj + 1], ah, bv[1], bv[3]);
            }
        }
    }

    float* op = g_opart + (size_t)kcnk * ((size_t)LQ * DIM);
#pragma unroll
    for (int n8 = 0; n8 < 8; n8++) {
        size_t row = (size_t)(q0 + qg + r0);
        size_t col = (size_t)(dh + n8 * 8 + c0);
        *(float2*)(op + row * DIM + col) = make_float2(o[n8][0], o[n8][1]);
        *(float2*)(op + (row + 8) * DIM + col) = make_float2(o[n8][2], o[n8][3]);
    }
}

// ---------------------------------------------------------------------------
// Kernel D: reduce KCH partials into out, applying il[row] once.
// ---------------------------------------------------------------------------
__global__ __launch_bounds__(256) void reduce_kernel(float* __restrict__ out) {
    const size_t i = (size_t)blockIdx.x * 256 + threadIdx.x;
    float s = 0.f;
#pragma unroll
    for (int c = 0; c < KCH; c++) s += g_opart[(size_t)c * LQ * DIM + i];
    out[i] = s * g_il[i >> 7];
}

// ---------------------------------------------------------------------------
extern "C" void kernel_launch(void* const* d_in, const int* in_sizes, int n_in,
                              void* d_out, int out_size) {
    const float* Q = (const float*)d_in[0];
    const float* K = (const float*)d_in[1];
    const float* V = (const float*)d_in[2];
    float* out = (float*)d_out;             // [LQ, DIM]
    float* att = out + (size_t)LQ * DIM;    // [LQ, LK]

    const int smemA = 2 * 128 * STRQ * 2;           // 69632
    const int smemC = 6 * 128 * STRP * 2 + 512;     // 111104
    cudaFuncSetAttribute(qk_hmma_kernel, cudaFuncAttributeMaxDynamicSharedMemorySize, smemA);
    cudaFuncSetAttribute(pv_hmma_kernel, cudaFuncAttributeMaxDynamicSharedMemorySize, smemC);

    prep_kernel<<<(LQ * DIM) / 256, 256>>>(Q, K, V);
    qk_hmma_kernel<<<dim3(LK / 128, LQ / 128), 256, smemA>>>();
    lred_kernel<<<LQ / 256, 256>>>();
    pv_hmma_kernel<<<dim3(KCH, LQ / 128), 512, smemC>>>(att);
    reduce_kernel<<<(LQ * DIM) / 256, 256>>>(out);
}